// round 5
// baseline (speedup 1.0000x reference)
#include <cuda_runtime.h>
#include <math.h>

#define SS 7
#define NCLS 20
#define TPB 256
#define NBLOCKS 784
#define NROW_TOTAL (8192 * 7 * 7)          // 401408
#define STRIDE (TPB * NBLOCKS)             // 200704 = NROW_TOTAL / 2
#define ROWS_PER_THREAD 2

// accumulators (zero at module load; reset by last block each invocation):
// 0: A (combined obj-side numerator), 1: B (noobj numerator),
// 2: sum_iou, 3: acc, 4: n_obj
__device__ double g_sums[5];
__device__ unsigned int g_count;

__device__ __forceinline__ void process_row(const float* __restrict__ outp,
                                            const float* __restrict__ tgtp,
                                            int r,
                                            float& accA, float& accB, float& accI,
                                            float& accC, float& accM) {
    // row base = 30*r floats = 120*r bytes -> float2 aligned
    const float2* o2 = (const float2*)(outp + (size_t)r * 30);
    const float2* g2 = (const float2*)(tgtp + (size_t)r * 30);

    // load full output row (30 floats = 15 float2)
    float ov[30];
#pragma unroll
    for (int j = 0; j < 15; j++) {
        float2 v = o2[j];
        ov[2 * j] = v.x;
        ov[2 * j + 1] = v.y;
    }
    // load target: g[0..5] (3 float2) and g[10..29] (10 float2).
    // tgt[5..9] duplicates tgt[0..4] (target = concat[box,conf,box,conf,cls]),
    // and g[9] == g[4], so we never need g[5..9].
    float gb[6];
#pragma unroll
    for (int j = 0; j < 3; j++) {
        float2 v = g2[j];
        gb[2 * j] = v.x;
        gb[2 * j + 1] = v.y;
    }
    float gc[20];
#pragma unroll
    for (int j = 0; j < 10; j++) {
        float2 v = g2[5 + j];            // floats 10..29
        gc[2 * j] = v.x;
        gc[2 * j + 1] = v.y;
    }

    const float m = (gb[4] > 0.0f) ? 1.0f : 0.0f;
    const float inv_s = 1.0f / (float)SS;

    // target box corners
    const float tx0 = gb[0] * inv_s - 0.5f * gb[2];
    const float ty0 = gb[1] * inv_s - 0.5f * gb[3];
    const float tx1 = gb[0] * inv_s + 0.5f * gb[2];
    const float ty1 = gb[1] * inv_s + 0.5f * gb[3];
    const float at  = (tx1 - tx0) * (ty1 - ty0);

    float iou[2];
#pragma unroll
    for (int b = 0; b < 2; b++) {
        const float* pb = ov + b * 5;
        const float px0 = pb[0] * inv_s - 0.5f * pb[2];
        const float py0 = pb[1] * inv_s - 0.5f * pb[3];
        const float px1 = pb[0] * inv_s + 0.5f * pb[2];
        const float py1 = pb[1] * inv_s + 0.5f * pb[3];
        const float ap  = (px1 - px0) * (py1 - py0);
        const float ulx = fmaxf(px0, tx0);
        const float uly = fmaxf(py0, ty0);
        const float lrx = fminf(px1, tx1);
        const float lry = fminf(py1, ty1);
        const float wi  = fmaxf(lrx - ulx, 0.0f);
        const float hi  = fmaxf(lry - uly, 0.0f);
        const float inter = wi * hi;
        iou[b] = inter / (ap + at - inter);
    }

    // argmax ties -> first index: box 1 wins only on strict >
    const int resp = (iou[1] > iou[0]) ? 1 : 0;
    const float max_iou = fmaxf(iou[0], iou[1]);
    const float min_iou = fminf(iou[0], iou[1]);

    const float* rb = ov + resp * 5;
    const float* nb = ov + (1 - resp) * 5;

    const float dx = rb[0] - gb[0];
    const float dy = rb[1] - gb[1];
    const float dw = sqrtf(rb[2]) - sqrtf(gb[2]);
    const float dh = sqrtf(rb[3]) - sqrtf(gb[3]);
    const float contain = dx * dx + dy * dy + dw * dw + dh * dh;

    const float d_obj = rb[4] - max_iou;
    const float objl  = d_obj * d_obj;
    const float notc  = nb[4] * nb[4];

    const float dn0 = ov[4] - gb[4];
    const float dn1 = ov[9] - gb[4];   // g[9] == g[4]
    const float noobj = dn0 * dn0 + dn1 * dn1;

    float cls = 0.0f;
    int pa = 0, ta = 0;
    float pbest = ov[10], tbest = gc[0];
#pragma unroll
    for (int k = 0; k < NCLS; k++) {
        const float po = ov[10 + k];
        const float tg = gc[k];
        const float d = po - tg;
        cls += d * d;
        if (po > pbest) { pbest = po; pa = k; }
        if (tg > tbest) { tbest = tg; ta = k; }
    }

    // loss = A_sum / n_obj + 0.25 * B_sum / n_noobj, with
    // A = m*(2.5*contain + obj + 0.5*notc + cls/20), B = (1-m)*noobj
    accA += m * (2.5f * contain + objl + 0.5f * notc + cls * (1.0f / (float)NCLS));
    accB += (1.0f - m) * noobj;
    accI += m * min_iou;
    accC += (m > 0.0f && pa == ta) ? 1.0f : 0.0f;
    accM += m;
}

__global__ void __launch_bounds__(TPB)
loss_reg_kernel(const float* __restrict__ outp_g, const float* __restrict__ tgt_g,
                float* __restrict__ res) {
    const int t = threadIdx.x;
    const int gtid = blockIdx.x * TPB + t;

    float accA = 0.0f, accB = 0.0f, accI = 0.0f, accC = 0.0f, accM = 0.0f;

#pragma unroll
    for (int i = 0; i < ROWS_PER_THREAD; i++) {
        process_row(outp_g, tgt_g, gtid + i * STRIDE, accA, accB, accI, accC, accM);
    }

    // ---- block reduction of 5 values (8 warps) ----
    float vals[5] = {accA, accB, accI, accC, accM};
#pragma unroll
    for (int off = 16; off > 0; off >>= 1) {
#pragma unroll
        for (int j = 0; j < 5; j++)
            vals[j] += __shfl_down_sync(0xFFFFFFFFu, vals[j], off);
    }

    __shared__ float s_red[8][5];
    const int warp = t >> 5;
    const int lane = t & 31;
    if (lane == 0) {
#pragma unroll
        for (int j = 0; j < 5; j++) s_red[warp][j] = vals[j];
    }
    __syncthreads();

    if (warp == 0 && lane < 5) {
        float s = 0.0f;
#pragma unroll
        for (int w = 0; w < 8; w++) s += s_red[w][lane];
        atomicAdd(&g_sums[lane], (double)s);
    }

    // ---- last-block finalize + reset ----
    __shared__ bool is_last;
    if (t == 0) {
        __threadfence();
        unsigned int v = atomicAdd(&g_count, 1u);
        is_last = (v == (unsigned int)(NBLOCKS - 1));
    }
    __syncthreads();

    if (is_last && t == 0) {
        const double sA = g_sums[0];
        const double sB = g_sums[1];
        const double sI = g_sums[2];
        const double sC = g_sums[3];
        const double sM = g_sums[4];

        const double n_obj   = sM;
        const double n_noobj = (double)NROW_TOTAL - n_obj;

        const double loss = sA / n_obj + 0.25 * sB / n_noobj;

        res[0] = (float)loss;
        res[1] = (float)sI;
        res[2] = (float)sC;

        // reset for next graph replay
#pragma unroll
        for (int j = 0; j < 5; j++) g_sums[j] = 0.0;
        __threadfence();
        g_count = 0u;
    }
}

extern "C" void kernel_launch(void* const* d_in, const int* in_sizes, int n_in,
                              void* d_out, int out_size) {
    const float* out_t = (const float*)d_in[0];
    const float* tgt_t = (const float*)d_in[1];
    float* res = (float*)d_out;

    loss_reg_kernel<<<NBLOCKS, TPB>>>(out_t, tgt_t, res);
}